// round 3
// baseline (speedup 1.0000x reference)
#include <cuda_runtime.h>
#include <math.h>

#define B_   128
#define M_   1024
#define DZ   1024
#define DPHI 512
#define H1   512
#define H2   512

// Scratch (allocation-free rule: __device__ globals).
__device__ float d_hz[B_ * H1];              // 256 KB : g_q @ W1[:DZ]
__device__ float d_hp[M_ * H1];              // 2 MB   : Phi @ W1[DZ:] + b1
__device__ float d_X [(size_t)B_ * M_ * H1]; // 268 MB : gelu(first layer)

__device__ __forceinline__ float gelu_exact(float x) {
    return 0.5f * x * (1.0f + erff(x * 0.70710678118654752f));
}

// ---------------------------------------------------------------------------
// Simple smem-tiled GEMM: C[M,N] = A[M,K] @ Bw[K,N] (+ bias). M,N,K % 16 == 0.
// Only 0.7 GFLOP total across both calls — not the bottleneck.
// ---------------------------------------------------------------------------
__global__ void gemm16(const float* __restrict__ A, const float* __restrict__ Bw,
                       const float* __restrict__ bias, float* __restrict__ C,
                       int M, int N, int K) {
    __shared__ float As[16][16];
    __shared__ float Bs[16][17];
    int ty = threadIdx.y, tx = threadIdx.x;
    int row = blockIdx.y * 16 + ty;
    int col = blockIdx.x * 16 + tx;
    float s = 0.f;
    for (int kk = 0; kk < K; kk += 16) {
        As[ty][tx] = A[(size_t)row * K + kk + tx];
        Bs[ty][tx] = Bw[(size_t)(kk + ty) * N + col];
        __syncthreads();
#pragma unroll
        for (int k = 0; k < 16; k++) s += As[ty][k] * Bs[k][tx];
        __syncthreads();
    }
    if (bias) s += bias[col];
    C[(size_t)row * N + col] = s;
}

// ---------------------------------------------------------------------------
// X[b][m][k] = gelu(hz[b][k] + hp[m][k])   (b1 already folded into hp)
// Memory-bound: 268 MB write, gelu computed exactly once per element.
// ---------------------------------------------------------------------------
__global__ void build_x(float* __restrict__ X) {
    size_t i4 = (size_t)blockIdx.x * blockDim.x + threadIdx.x; // float4 index
    size_t total4 = (size_t)B_ * M_ * H1 / 4;
    if (i4 >= total4) return;
    int k4 = (int)(i4 % (H1 / 4));
    size_t t = i4 / (H1 / 4);
    int m = (int)(t % M_);
    int b = (int)(t / M_);
    const float4* hz4 = (const float4*)d_hz;
    const float4* hp4 = (const float4*)d_hp;
    float4 z = hz4[(size_t)b * (H1 / 4) + k4];
    float4 p = hp4[(size_t)m * (H1 / 4) + k4];
    float4 r;
    r.x = gelu_exact(z.x + p.x);
    r.y = gelu_exact(z.y + p.y);
    r.z = gelu_exact(z.z + p.z);
    r.w = gelu_exact(z.w + p.w);
    ((float4*)X)[i4] = r;
}

// ---------------------------------------------------------------------------
// Main fused kernel: for one (b, 128-row m-tile):
//   C = X_tile[128,512] @ W2[512,512]  (in 4 col-chunks of 128)
//   u[row] = b3 + sum_col gelu(C + b2[col]) * W3[col]
// 256 threads, 8x8 register blocking, double-buffered smem (register prefetch,
// ONE barrier per k-tile), shuffle-reduced epilogue (no atomics).
// ---------------------------------------------------------------------------
__global__ __launch_bounds__(256, 2)
void fused_mlp2(const float* __restrict__ X, const float* __restrict__ W2,
                const float* __restrict__ b2, const float* __restrict__ W3,
                const float* __restrict__ b3p, float* __restrict__ out) {
    const int b  = blockIdx.y;
    const int m0 = blockIdx.x * 128;
    const float* Xrow = X + ((size_t)b * M_ + m0) * H1;

    __shared__ float Xs[2][16][132];  // [buf][k][row]
    __shared__ float Ws[2][16][132];  // [buf][k][col]
    __shared__ float rowacc[128];

    const int tid = threadIdx.x;
    const int tx = tid & 15;   // col group
    const int ty = tid >> 4;   // row group

    if (tid < 128) rowacc[tid] = 0.f;

    // Load-index precompute
    const int xrow = (tid >> 2) & 63;       // 0..63 (and +64)
    const int xkq  = (tid & 3) * 4;         // 0,4,8,12
    const int wcol = (tid & 31) * 4;        // 0..124
    const int wk   = tid >> 5;              // 0..7 (and +8)

    const int NKT = H1 / 16;                // 32 k-tiles

    for (int cc = 0; cc < 4; cc++) {
        float acc[8][8];
#pragma unroll
        for (int i = 0; i < 8; i++)
#pragma unroll
            for (int j = 0; j < 8; j++) acc[i][j] = 0.f;

        const int colg = cc * 128;

        // ---- prologue: tile 0 -> buf 0 ----
        {
            float4 v0 = *(const float4*)(Xrow + (size_t)xrow * H1 + xkq);
            float4 v1 = *(const float4*)(Xrow + (size_t)(xrow + 64) * H1 + xkq);
            float4 w0 = *(const float4*)(W2 + (size_t)wk * H2 + colg + wcol);
            float4 w1 = *(const float4*)(W2 + (size_t)(wk + 8) * H2 + colg + wcol);
            Xs[0][xkq + 0][xrow] = v0.x; Xs[0][xkq + 1][xrow] = v0.y;
            Xs[0][xkq + 2][xrow] = v0.z; Xs[0][xkq + 3][xrow] = v0.w;
            Xs[0][xkq + 0][xrow + 64] = v1.x; Xs[0][xkq + 1][xrow + 64] = v1.y;
            Xs[0][xkq + 2][xrow + 64] = v1.z; Xs[0][xkq + 3][xrow + 64] = v1.w;
            *(float4*)&Ws[0][wk][wcol]     = w0;
            *(float4*)&Ws[0][wk + 8][wcol] = w1;
        }
        __syncthreads();

        for (int kt = 0; kt < NKT; kt++) {
            const int buf = kt & 1;
            float4 nv0, nv1, nw0, nw1;
            if (kt + 1 < NKT) {
                const int kn = (kt + 1) * 16;
                nv0 = *(const float4*)(Xrow + (size_t)xrow * H1 + kn + xkq);
                nv1 = *(const float4*)(Xrow + (size_t)(xrow + 64) * H1 + kn + xkq);
                nw0 = *(const float4*)(W2 + (size_t)(kn + wk) * H2 + colg + wcol);
                nw1 = *(const float4*)(W2 + (size_t)(kn + wk + 8) * H2 + colg + wcol);
            }
#pragma unroll
            for (int ki = 0; ki < 16; ki++) {
                float4 a0 = *(const float4*)&Xs[buf][ki][ty * 4];
                float4 a1 = *(const float4*)&Xs[buf][ki][64 + ty * 4];
                float4 w0 = *(const float4*)&Ws[buf][ki][tx * 4];
                float4 w1 = *(const float4*)&Ws[buf][ki][64 + tx * 4];
                float a[8] = {a0.x, a0.y, a0.z, a0.w, a1.x, a1.y, a1.z, a1.w};
                float w[8] = {w0.x, w0.y, w0.z, w0.w, w1.x, w1.y, w1.z, w1.w};
#pragma unroll
                for (int i = 0; i < 8; i++)
#pragma unroll
                    for (int j = 0; j < 8; j++) acc[i][j] += a[i] * w[j];
            }
            if (kt + 1 < NKT) {
                const int nb = buf ^ 1;
                // Writes go to the OTHER buffer; safe while peers still read buf.
                Xs[nb][xkq + 0][xrow] = nv0.x; Xs[nb][xkq + 1][xrow] = nv0.y;
                Xs[nb][xkq + 2][xrow] = nv0.z; Xs[nb][xkq + 3][xrow] = nv0.w;
                Xs[nb][xkq + 0][xrow + 64] = nv1.x; Xs[nb][xkq + 1][xrow + 64] = nv1.y;
                Xs[nb][xkq + 2][xrow + 64] = nv1.z; Xs[nb][xkq + 3][xrow + 64] = nv1.w;
                *(float4*)&Ws[nb][wk][wcol]     = nw0;
                *(float4*)&Ws[nb][wk + 8][wcol] = nw1;
            }
            __syncthreads();
        }

        // Epilogue: gelu(+b2) * W3, shuffle-reduce the 16 tx lanes per row.
        float w3v[8], b2v[8];
#pragma unroll
        for (int j = 0; j < 8; j++) {
            int col = colg + ((j < 4) ? (tx * 4 + j) : (64 + tx * 4 + (j - 4)));
            w3v[j] = W3[col];
            b2v[j] = b2[col];
        }
#pragma unroll
        for (int i = 0; i < 8; i++) {
            float s = 0.f;
#pragma unroll
            for (int j = 0; j < 8; j++) {
                float v = gelu_exact(acc[i][j] + b2v[j]);
                s += v * w3v[j];
            }
            // Reduce across the 16 tx lanes (same warp half shares ty).
            s += __shfl_xor_sync(0xffffffffu, s, 1);
            s += __shfl_xor_sync(0xffffffffu, s, 2);
            s += __shfl_xor_sync(0xffffffffu, s, 4);
            s += __shfl_xor_sync(0xffffffffu, s, 8);
            if (tx == 0) {
                int row = (i < 4) ? (ty * 4 + i) : (64 + ty * 4 + (i - 4));
                rowacc[row] += s;   // unique owner (ty,i) — no atomic needed
            }
        }
        __syncthreads();
    }

    if (tid < 128)
        out[(size_t)b * M_ + m0 + tid] = rowacc[tid] + b3p[0];
}

// ---------------------------------------------------------------------------
extern "C" void kernel_launch(void* const* d_in, const int* in_sizes, int n_in,
                              void* d_out, int out_size) {
    const float* g_q = (const float*)d_in[0];  // [128,1024]
    const float* Phi = (const float*)d_in[1];  // [1024,512]
    const float* W1  = (const float*)d_in[2];  // [1536,512]
    const float* b1  = (const float*)d_in[3];  // [512]
    const float* W2  = (const float*)d_in[4];  // [512,512]
    const float* b2  = (const float*)d_in[5];  // [512]
    const float* W3  = (const float*)d_in[6];  // [512,1]
    const float* b3  = (const float*)d_in[7];  // [1]
    float* out = (float*)d_out;                // [128,1024]

    float* hz; cudaGetSymbolAddress((void**)&hz, d_hz);
    float* hp; cudaGetSymbolAddress((void**)&hp, d_hp);
    float* X;  cudaGetSymbolAddress((void**)&X,  d_X);

    // hz = g_q @ W1[:DZ]            [128, 512]
    gemm16<<<dim3(H1 / 16, B_ / 16), dim3(16, 16)>>>(g_q, W1, nullptr, hz, B_, H1, DZ);
    // hp = Phi @ W1[DZ:] + b1       [1024, 512]
    gemm16<<<dim3(H1 / 16, M_ / 16), dim3(16, 16)>>>(Phi, W1 + (size_t)DZ * H1, b1, hp, M_, H1, DPHI);
    // X = gelu(hz[b] + hp[m])       [128, 1024, 512]
    {
        size_t total4 = (size_t)B_ * M_ * H1 / 4;
        int threads = 256;
        int blocks = (int)((total4 + threads - 1) / threads);
        build_x<<<blocks, threads>>>(X);
    }
    // u = (gelu(X @ W2 + b2)) @ W3 + b3
    fused_mlp2<<<dim3(M_ / 128, B_), 256>>>(X, W2, b2, W3, b3, out);
}

// round 14
// speedup vs baseline: 2.8602x; 2.8602x over previous
#include <cuda_runtime.h>
#include <cuda_bf16.h>
#include <math.h>
#include <stdint.h>

#define B_   128
#define M_   1024
#define DZ   1024
#define DPHI 512
#define H1   512
#define H2   512
#define RT   (B_*M_)          // 131072 total rows

// ---------------- scratch (__device__ globals; no allocs allowed) ----------
__device__ float d_hz[B_ * H1];                     // g_q @ W1[:DZ]
__device__ float d_hp[M_ * H1];                     // Phi @ W1[DZ:] + b1
__device__ __nv_bfloat16 d_Xhi[(size_t)RT * H1];    // 134 MB
__device__ __nv_bfloat16 d_Xlo[(size_t)RT * H1];    // 134 MB
__device__ __nv_bfloat16 d_Whi[H2 * H1];            // W2^T hi  [n][k]
__device__ __nv_bfloat16 d_Wlo[H2 * H1];            // W2^T lo  [n][k]
__device__ float d_part[4 * RT];                    // per-col-CTA partial sums

__device__ __forceinline__ float gelu_exact(float x) {
    return 0.5f * x * (1.0f + erff(x * 0.70710678118654752f));
}
__device__ __forceinline__ uint32_t smem_u32(const void* p) {
    uint32_t a;
    asm("{ .reg .u64 t; cvta.to.shared.u64 t, %1; cvt.u32.u64 %0, t; }" : "=r"(a) : "l"(p));
    return a;
}

// Baseline (non-'a') tensor-core primitives — compile for plain sm_103.
#define LDSM_X4(r, addr)                                                        \
    asm volatile("ldmatrix.sync.aligned.m8n8.x4.shared.b16 {%0,%1,%2,%3}, [%4];"\
        : "=r"((r)[0]), "=r"((r)[1]), "=r"((r)[2]), "=r"((r)[3]) : "r"(addr))
#define LDSM_X2(r, addr)                                                        \
    asm volatile("ldmatrix.sync.aligned.m8n8.x2.shared.b16 {%0,%1}, [%2];"      \
        : "=r"((r)[0]), "=r"((r)[1]) : "r"(addr))
#define MMA_BF16(d, a, b)                                                       \
    asm volatile("mma.sync.aligned.m16n8k16.row.col.f32.bf16.bf16.f32 "         \
        "{%0,%1,%2,%3}, {%4,%5,%6,%7}, {%8,%9}, {%0,%1,%2,%3};"                 \
        : "+f"((d)[0]), "+f"((d)[1]), "+f"((d)[2]), "+f"((d)[3])                \
        : "r"((a)[0]), "r"((a)[1]), "r"((a)[2]), "r"((a)[3]),                   \
          "r"((b)[0]), "r"((b)[1]))

// ---------------------------------------------------------------------------
// First-layer GEMM: 64x64 tile, 256 threads, 4x4 microtile, float4 loads.
// ---------------------------------------------------------------------------
__global__ __launch_bounds__(256)
void gemm64(const float* __restrict__ A, const float* __restrict__ Bw,
            const float* __restrict__ bias, float* __restrict__ C,
            int M, int N, int K) {
    __shared__ float As[16][68];
    __shared__ float Bs[16][68];
    const int tid = threadIdx.x;
    const int tx = tid & 15;
    const int ty = tid >> 4;
    const int row0 = blockIdx.y * 64;
    const int col0 = blockIdx.x * 64;
    const int arow = tid >> 2;
    const int akq  = (tid & 3) * 4;
    const int bk   = tid >> 4;
    const int bc4  = (tid & 15) * 4;

    float acc[4][4];
#pragma unroll
    for (int i = 0; i < 4; i++)
#pragma unroll
        for (int j = 0; j < 4; j++) acc[i][j] = 0.f;

    for (int kk = 0; kk < K; kk += 16) {
        float4 av = *(const float4*)(A + (size_t)(row0 + arow) * K + kk + akq);
        float4 bv = *(const float4*)(Bw + (size_t)(kk + bk) * N + col0 + bc4);
        As[akq + 0][arow] = av.x; As[akq + 1][arow] = av.y;
        As[akq + 2][arow] = av.z; As[akq + 3][arow] = av.w;
        *(float4*)&Bs[bk][bc4] = bv;
        __syncthreads();
#pragma unroll
        for (int k = 0; k < 16; k++) {
            float4 a4 = *(const float4*)&As[k][ty * 4];
            float4 b4 = *(const float4*)&Bs[k][tx * 4];
            float a[4] = {a4.x, a4.y, a4.z, a4.w};
            float b[4] = {b4.x, b4.y, b4.z, b4.w};
#pragma unroll
            for (int i = 0; i < 4; i++)
#pragma unroll
                for (int j = 0; j < 4; j++) acc[i][j] += a[i] * b[j];
        }
        __syncthreads();
    }

    float bv[4] = {0.f, 0.f, 0.f, 0.f};
    if (bias) {
#pragma unroll
        for (int j = 0; j < 4; j++) bv[j] = bias[col0 + tx * 4 + j];
    }
#pragma unroll
    for (int i = 0; i < 4; i++) {
        float4 o;
        o.x = acc[i][0] + bv[0]; o.y = acc[i][1] + bv[1];
        o.z = acc[i][2] + bv[2]; o.w = acc[i][3] + bv[3];
        *(float4*)(C + (size_t)(row0 + ty * 4 + i) * N + col0 + tx * 4) = o;
    }
}

// ---------------------------------------------------------------------------
// X = gelu(hz[b] + hp[m]) split into bf16 hi/lo pairs.
// ---------------------------------------------------------------------------
__global__ void build_x_split(__nv_bfloat16* __restrict__ Xhi,
                              __nv_bfloat16* __restrict__ Xlo) {
    size_t i4 = (size_t)blockIdx.x * blockDim.x + threadIdx.x;
    if (i4 >= (size_t)RT * H1 / 4) return;
    int k4 = (int)(i4 & 127);
    size_t r = i4 >> 7;
    int m = (int)(r & (M_ - 1));
    int b = (int)(r >> 10);
    float4 z = ((const float4*)d_hz)[(size_t)b * 128 + k4];
    float4 p = ((const float4*)d_hp)[(size_t)m * 128 + k4];
    float x0 = gelu_exact(z.x + p.x), x1 = gelu_exact(z.y + p.y);
    float x2 = gelu_exact(z.z + p.z), x3 = gelu_exact(z.w + p.w);
    __nv_bfloat16 h0 = __float2bfloat16_rn(x0), h1 = __float2bfloat16_rn(x1);
    __nv_bfloat16 h2 = __float2bfloat16_rn(x2), h3 = __float2bfloat16_rn(x3);
    __nv_bfloat16 l0 = __float2bfloat16_rn(x0 - __bfloat162float(h0));
    __nv_bfloat16 l1 = __float2bfloat16_rn(x1 - __bfloat162float(h1));
    __nv_bfloat16 l2 = __float2bfloat16_rn(x2 - __bfloat162float(h2));
    __nv_bfloat16 l3 = __float2bfloat16_rn(x3 - __bfloat162float(h3));
    uint2 uh, ul;
    uh.x = ((uint32_t)__bfloat16_as_ushort(h1) << 16) | __bfloat16_as_ushort(h0);
    uh.y = ((uint32_t)__bfloat16_as_ushort(h3) << 16) | __bfloat16_as_ushort(h2);
    ul.x = ((uint32_t)__bfloat16_as_ushort(l1) << 16) | __bfloat16_as_ushort(l0);
    ul.y = ((uint32_t)__bfloat16_as_ushort(l3) << 16) | __bfloat16_as_ushort(l2);
    ((uint2*)Xhi)[i4] = uh;
    ((uint2*)Xlo)[i4] = ul;
}

// W2^T split: Whi/Wlo[n*512 + k] = split(W2[k*512 + n])
__global__ void w2_split(const float* __restrict__ W2,
                         __nv_bfloat16* __restrict__ Whi,
                         __nv_bfloat16* __restrict__ Wlo) {
    int i = blockIdx.x * 256 + threadIdx.x;
    if (i >= H1 * H2) return;
    int n = i >> 9, k = i & 511;
    float w = W2[(size_t)k * H2 + n];
    __nv_bfloat16 h = __float2bfloat16_rn(w);
    __nv_bfloat16 l = __float2bfloat16_rn(w - __bfloat162float(h));
    Whi[i] = h;
    Wlo[i] = l;
}

// ---------------------------------------------------------------------------
// Main GEMM via mma.sync (HMMA, baseline PTX — compiles for plain sm_103).
// CTA: 128 rows x 128 cols. 8 warps (4 m x 2 n), warp tile 32x64.
// K=512 in 8 chunks of 64. 3 split-bf16 passes (AhBh+AhBl+AlBh) reuse smem.
// smem/chunk: Ahi@0, Alo@16K, Bhi@32K, Blo@48K (128B rows, SW128 swizzle).
// Fused epilogue: u_part[row] = sum_col gelu(C+b2[col]) * W3[col].
// ---------------------------------------------------------------------------
#define MAIN_SMEM 65536

__global__ __launch_bounds__(256, 2)
void main_mma_sync(const __nv_bfloat16* __restrict__ Xhi, const __nv_bfloat16* __restrict__ Xlo,
                   const __nv_bfloat16* __restrict__ Whi, const __nv_bfloat16* __restrict__ Wlo,
                   const float* __restrict__ b2, const float* __restrict__ W3,
                   float* __restrict__ part) {
    extern __shared__ char smem[];
    __shared__ float rowpart[128];

    const int tid  = threadIdx.x;
    const int wid  = tid >> 5, lane = tid & 31;
    const int warp_m = wid & 3;       // rows warp_m*32 .. +31
    const int warp_n = wid >> 2;      // cols warp_n*64 .. +63 (local)
    const int bx = blockIdx.x;        // col CTA: cols bx*128 ..
    const int r0 = blockIdx.y << 7;   // row tile base
    const int n0 = bx << 7;
    const uint32_t sb = smem_u32(smem);

    float acc[2][8][4];
#pragma unroll
    for (int i = 0; i < 2; i++)
#pragma unroll
        for (int j = 0; j < 8; j++)
#pragma unroll
            for (int k = 0; k < 4; k++) acc[i][j][k] = 0.f;

    for (int c = 0; c < 8; c++) {
        __syncthreads();   // smem reuse guard (no-op cost on c==0)
        // A tiles: 128 rows x 64 bf16 (128 B/row, SW128), hi then lo
        for (int idx = tid; idx < 2048; idx += 256) {
            int arr = idx >> 10;
            int e = idx & 1023, row = e >> 3, q = e & 7;
            const __nv_bfloat16* s = (arr ? Xlo : Xhi) + (size_t)(r0 + row) * H1 + c * 64 + q * 8;
            uint4 v = *(const uint4*)s;
            uint32_t off = (uint32_t)((row << 7) + (q << 4));
            off ^= (off >> 3) & 0x70;
            *(uint4*)(smem + (arr << 14) + off) = v;
        }
        // B tiles: 128 n-rows x 64 bf16, hi then lo
        for (int idx = tid; idx < 2048; idx += 256) {
            int arr = idx >> 10;
            int e = idx & 1023, row = e >> 3, q = e & 7;
            const __nv_bfloat16* s = (arr ? Wlo : Whi) + (size_t)(n0 + row) * H1 + c * 64 + q * 8;
            uint4 v = *(const uint4*)s;
            uint32_t off = (uint32_t)((row << 7) + (q << 4));
            off ^= (off >> 3) & 0x70;
            *(uint4*)(smem + 32768 + (arr << 14) + off) = v;
        }
        __syncthreads();

#pragma unroll
        for (int ks = 0; ks < 4; ks++) {
            uint32_t ah[2][4], al[2][4];
#pragma unroll
            for (int mi = 0; mi < 2; mi++) {
                int rowa = warp_m * 32 + mi * 16 + (lane & 15);
                int chka = ks * 2 + (lane >> 4);
                uint32_t offa = (uint32_t)(rowa * 128 + ((chka ^ (rowa & 7)) << 4));
                LDSM_X4(ah[mi], sb + offa);
                LDSM_X4(al[mi], sb + 16384 + offa);
            }
#pragma unroll
            for (int nh = 0; nh < 2; nh++) {
                uint32_t bh[4][2], bl[4][2];
#pragma unroll
                for (int ni = 0; ni < 4; ni++) {
                    int rowb = warp_n * 64 + nh * 32 + ni * 8 + (lane & 7);
                    int chkb = ks * 2 + ((lane >> 3) & 1);
                    uint32_t offb = (uint32_t)(rowb * 128 + ((chkb ^ (rowb & 7)) << 4));
                    LDSM_X2(bh[ni], sb + 32768 + offb);
                    LDSM_X2(bl[ni], sb + 49152 + offb);
                }
#pragma unroll
                for (int mi = 0; mi < 2; mi++)
#pragma unroll
                    for (int ni = 0; ni < 4; ni++) {
                        float* d = acc[mi][nh * 4 + ni];
                        MMA_BF16(d, ah[mi], bh[ni]);   // AhBh
                        MMA_BF16(d, ah[mi], bl[ni]);   // AhBl
                        MMA_BF16(d, al[mi], bh[ni]);   // AlBh
                    }
            }
        }
    }

    // Epilogue: gelu(c + b2)*W3, reduce over this CTA's 128 cols per row.
    // C frag: thread lane: rows {g, g+8} per m-tile (g=lane>>2), cols (lane&3)*2+{0,1}.
    const int g  = lane >> 2;
    const int cq = lane & 3;
    float rs[4] = {0.f, 0.f, 0.f, 0.f};   // rows: mi*16 + h*8 + g
#pragma unroll
    for (int mi = 0; mi < 2; mi++)
#pragma unroll
        for (int nh = 0; nh < 2; nh++)
#pragma unroll
            for (int ni = 0; ni < 4; ni++)
#pragma unroll
                for (int h = 0; h < 2; h++)
#pragma unroll
                    for (int cc = 0; cc < 2; cc++) {
                        int col = n0 + warp_n * 64 + nh * 32 + ni * 8 + cq * 2 + cc;
                        float v = gelu_exact(acc[mi][nh * 4 + ni][h * 2 + cc] + __ldg(&b2[col]))
                                  * __ldg(&W3[col]);
                        rs[mi * 2 + h] += v;
                    }
#pragma unroll
    for (int j = 0; j < 4; j++) {
        rs[j] += __shfl_xor_sync(0xffffffffu, rs[j], 1);
        rs[j] += __shfl_xor_sync(0xffffffffu, rs[j], 2);
    }
    __syncthreads();
    if (warp_n == 0 && cq == 0) {
#pragma unroll
        for (int j = 0; j < 4; j++)
            rowpart[warp_m * 32 + (j >> 1) * 16 + (j & 1) * 8 + g] = rs[j];
    }
    __syncthreads();
    if (warp_n == 1 && cq == 0) {
#pragma unroll
        for (int j = 0; j < 4; j++)
            rowpart[warp_m * 32 + (j >> 1) * 16 + (j & 1) * 8 + g] += rs[j];
    }
    __syncthreads();
    if (tid < 128)
        part[(size_t)bx * RT + r0 + tid] = rowpart[tid];
}

// out = sum of 4 col-CTA partials + b3 (deterministic fp32 combine)
__global__ void combine_k(const float* __restrict__ part, const float* __restrict__ b3,
                          float* __restrict__ out) {
    int i = blockIdx.x * 256 + threadIdx.x;
    if (i < RT)
        out[i] = part[i] + part[RT + i] + part[2 * RT + i] + part[3 * RT + i] + b3[0];
}

// ---------------------------------------------------------------------------
extern "C" void kernel_launch(void* const* d_in, const int* in_sizes, int n_in,
                              void* d_out, int out_size) {
    const float* g_q = (const float*)d_in[0];
    const float* Phi = (const float*)d_in[1];
    const float* W1  = (const float*)d_in[2];
    const float* b1  = (const float*)d_in[3];
    const float* W2  = (const float*)d_in[4];
    const float* b2  = (const float*)d_in[5];
    const float* W3  = (const float*)d_in[6];
    const float* b3  = (const float*)d_in[7];
    float* out = (float*)d_out;

    float* hz; cudaGetSymbolAddress((void**)&hz, d_hz);
    float* hp; cudaGetSymbolAddress((void**)&hp, d_hp);
    __nv_bfloat16* Xhi; cudaGetSymbolAddress((void**)&Xhi, d_Xhi);
    __nv_bfloat16* Xlo; cudaGetSymbolAddress((void**)&Xlo, d_Xlo);
    __nv_bfloat16* Whi; cudaGetSymbolAddress((void**)&Whi, d_Whi);
    __nv_bfloat16* Wlo; cudaGetSymbolAddress((void**)&Wlo, d_Wlo);
    float* part; cudaGetSymbolAddress((void**)&part, d_part);

    // First layer (small)
    gemm64<<<dim3(H1 / 64, B_ / 64), 256>>>(g_q, W1, nullptr, hz, B_, H1, DZ);
    gemm64<<<dim3(H1 / 64, M_ / 64), 256>>>(Phi, W1 + (size_t)DZ * H1, b1, hp, M_, H1, DPHI);
    // Split inputs for tensor cores
    w2_split<<<(H1 * H2 + 255) / 256, 256>>>(W2, Whi, Wlo);
    {
        size_t total4 = (size_t)RT * H1 / 4;
        build_x_split<<<(unsigned)((total4 + 255) / 256), 256>>>(Xhi, Xlo);
    }
    // Main HMMA GEMM + fused gelu/W3 epilogue
    cudaFuncSetAttribute(main_mma_sync, cudaFuncAttributeMaxDynamicSharedMemorySize, MAIN_SMEM);
    main_mma_sync<<<dim3(H2 / 128, RT / 128), 256, MAIN_SMEM>>>(Xhi, Xlo, Whi, Wlo, b2, W3, part);
    // Combine col-CTA partials + b3
    combine_k<<<RT / 256, 256>>>(part, b3, out);
}

// round 15
// speedup vs baseline: 3.2295x; 1.1291x over previous
#include <cuda_runtime.h>
#include <cuda_fp16.h>
#include <math.h>
#include <stdint.h>

#define B_   128
#define M_   1024
#define DZ   1024
#define DPHI 512
#define H1   512
#define H2   512
#define RT   (B_*M_)          // 131072 total rows

// ---------------- scratch (__device__ globals; no allocs allowed) ----------
__device__ float d_hz[B_ * H1];                 // g_q @ W1[:DZ]
__device__ float d_hp[M_ * H1];                 // Phi @ W1[DZ:] + b1
__device__ __half d_Xh[(size_t)RT * H1];        // 134 MB : fp16(gelu(first layer))
__device__ __half d_Whf[H2 * H1];               // W2^T hi  [n][k] fp16
__device__ __half d_Wlf[H2 * H1];               // W2^T lo  [n][k] fp16
__device__ float d_part[4 * RT];                // per-col-CTA partial sums

__device__ __forceinline__ float gelu_exact(float x) {
    return 0.5f * x * (1.0f + erff(x * 0.70710678118654752f));
}
__device__ __forceinline__ uint32_t smem_u32(const void* p) {
    uint32_t a;
    asm("{ .reg .u64 t; cvta.to.shared.u64 t, %1; cvt.u32.u64 %0, t; }" : "=r"(a) : "l"(p));
    return a;
}

// Baseline (non-'a') tensor-core primitives — compile for plain sm_103.
#define LDSM_X4(r, addr)                                                        \
    asm volatile("ldmatrix.sync.aligned.m8n8.x4.shared.b16 {%0,%1,%2,%3}, [%4];"\
        : "=r"((r)[0]), "=r"((r)[1]), "=r"((r)[2]), "=r"((r)[3]) : "r"(addr))
#define LDSM_X2(r, addr)                                                        \
    asm volatile("ldmatrix.sync.aligned.m8n8.x2.shared.b16 {%0,%1}, [%2];"      \
        : "=r"((r)[0]), "=r"((r)[1]) : "r"(addr))
#define MMA_F16(d, a, b)                                                        \
    asm volatile("mma.sync.aligned.m16n8k16.row.col.f32.f16.f16.f32 "           \
        "{%0,%1,%2,%3}, {%4,%5,%6,%7}, {%8,%9}, {%0,%1,%2,%3};"                 \
        : "+f"((d)[0]), "+f"((d)[1]), "+f"((d)[2]), "+f"((d)[3])                \
        : "r"((a)[0]), "r"((a)[1]), "r"((a)[2]), "r"((a)[3]),                   \
          "r"((b)[0]), "r"((b)[1]))

// ---------------------------------------------------------------------------
// First-layer GEMM: 64x64 tile, 256 threads, 4x4 microtile, float4 loads.
// ---------------------------------------------------------------------------
__global__ __launch_bounds__(256)
void gemm64(const float* __restrict__ A, const float* __restrict__ Bw,
            const float* __restrict__ bias, float* __restrict__ C,
            int M, int N, int K) {
    __shared__ float As[16][68];
    __shared__ float Bs[16][68];
    const int tid = threadIdx.x;
    const int tx = tid & 15;
    const int ty = tid >> 4;
    const int row0 = blockIdx.y * 64;
    const int col0 = blockIdx.x * 64;
    const int arow = tid >> 2;
    const int akq  = (tid & 3) * 4;
    const int bk   = tid >> 4;
    const int bc4  = (tid & 15) * 4;

    float acc[4][4];
#pragma unroll
    for (int i = 0; i < 4; i++)
#pragma unroll
        for (int j = 0; j < 4; j++) acc[i][j] = 0.f;

    for (int kk = 0; kk < K; kk += 16) {
        float4 av = *(const float4*)(A + (size_t)(row0 + arow) * K + kk + akq);
        float4 bv = *(const float4*)(Bw + (size_t)(kk + bk) * N + col0 + bc4);
        As[akq + 0][arow] = av.x; As[akq + 1][arow] = av.y;
        As[akq + 2][arow] = av.z; As[akq + 3][arow] = av.w;
        *(float4*)&Bs[bk][bc4] = bv;
        __syncthreads();
#pragma unroll
        for (int k = 0; k < 16; k++) {
            float4 a4 = *(const float4*)&As[k][ty * 4];
            float4 b4 = *(const float4*)&Bs[k][tx * 4];
            float a[4] = {a4.x, a4.y, a4.z, a4.w};
            float b[4] = {b4.x, b4.y, b4.z, b4.w};
#pragma unroll
            for (int i = 0; i < 4; i++)
#pragma unroll
                for (int j = 0; j < 4; j++) acc[i][j] += a[i] * b[j];
        }
        __syncthreads();
    }

    float bv[4] = {0.f, 0.f, 0.f, 0.f};
    if (bias) {
#pragma unroll
        for (int j = 0; j < 4; j++) bv[j] = bias[col0 + tx * 4 + j];
    }
#pragma unroll
    for (int i = 0; i < 4; i++) {
        float4 o;
        o.x = acc[i][0] + bv[0]; o.y = acc[i][1] + bv[1];
        o.z = acc[i][2] + bv[2]; o.w = acc[i][3] + bv[3];
        *(float4*)(C + (size_t)(row0 + ty * 4 + i) * N + col0 + tx * 4) = o;
    }
}

// ---------------------------------------------------------------------------
// X = fp16(gelu(hz[b] + hp[m])) — single array, A needs no split (11-bit hi).
// ---------------------------------------------------------------------------
__global__ void build_x_h(__half* __restrict__ Xh) {
    size_t i4 = (size_t)blockIdx.x * blockDim.x + threadIdx.x;
    if (i4 >= (size_t)RT * H1 / 4) return;
    int k4 = (int)(i4 & 127);
    size_t r = i4 >> 7;
    int m = (int)(r & (M_ - 1));
    int b = (int)(r >> 10);
    float4 z = ((const float4*)d_hz)[(size_t)b * 128 + k4];
    float4 p = ((const float4*)d_hp)[(size_t)m * 128 + k4];
    __half h0 = __float2half_rn(gelu_exact(z.x + p.x));
    __half h1 = __float2half_rn(gelu_exact(z.y + p.y));
    __half h2 = __float2half_rn(gelu_exact(z.z + p.z));
    __half h3 = __float2half_rn(gelu_exact(z.w + p.w));
    uint2 u;
    u.x = ((uint32_t)__half_as_ushort(h1) << 16) | __half_as_ushort(h0);
    u.y = ((uint32_t)__half_as_ushort(h3) << 16) | __half_as_ushort(h2);
    ((uint2*)Xh)[i4] = u;
}

// W2^T split into fp16 hi/lo: W = Whf + Wlf (11+11 bits ≈ fp32 accuracy)
__global__ void w2_split(const float* __restrict__ W2,
                         __half* __restrict__ Whf,
                         __half* __restrict__ Wlf) {
    int i = blockIdx.x * 256 + threadIdx.x;
    if (i >= H1 * H2) return;
    int n = i >> 9, k = i & 511;
    float w = W2[(size_t)k * H2 + n];
    __half h = __float2half_rn(w);
    __half l = __float2half_rn(w - __half2float(h));
    Whf[i] = h;
    Wlf[i] = l;
}

// ---------------------------------------------------------------------------
// Main GEMM via mma.sync fp16 (HMMA, baseline PTX).
// CTA: 128 rows x 128 cols. 8 warps (4 m x 2 n), warp tile 32x64.
// K=512 in 8 chunks of 64. TWO passes: Xh*Wh + Xh*Wl (X unsplit fp16).
// smem/chunk: A@0 (16K), Bh@16K, Bl@32K (128B rows, SW128 swizzle). 48KB.
// Fused epilogue: u_part[row] = sum_col gelu(C+b2[col]) * W3[col].
// ---------------------------------------------------------------------------
#define MAIN_SMEM 49152

__global__ __launch_bounds__(256, 2)
void main_mma_sync(const __half* __restrict__ Xh,
                   const __half* __restrict__ Whf, const __half* __restrict__ Wlf,
                   const float* __restrict__ b2, const float* __restrict__ W3,
                   float* __restrict__ part) {
    extern __shared__ char smem[];
    __shared__ float rowpart[128];

    const int tid  = threadIdx.x;
    const int wid  = tid >> 5, lane = tid & 31;
    const int warp_m = wid & 3;       // rows warp_m*32 .. +31
    const int warp_n = wid >> 2;      // cols warp_n*64 .. +63 (local)
    const int bx = blockIdx.x;        // col CTA: cols bx*128 ..
    const int r0 = blockIdx.y << 7;   // row tile base
    const int n0 = bx << 7;
    const uint32_t sb = smem_u32(smem);

    float acc[2][8][4];
#pragma unroll
    for (int i = 0; i < 2; i++)
#pragma unroll
        for (int j = 0; j < 8; j++)
#pragma unroll
            for (int k = 0; k < 4; k++) acc[i][j][k] = 0.f;

    for (int c = 0; c < 8; c++) {
        __syncthreads();   // smem reuse guard
        // A tile: 128 rows x 64 fp16 (128 B/row, SW128)
        for (int idx = tid; idx < 1024; idx += 256) {
            int row = idx >> 3, q = idx & 7;
            const __half* s = Xh + (size_t)(r0 + row) * H1 + c * 64 + q * 8;
            uint4 v = *(const uint4*)s;
            uint32_t off = (uint32_t)((row << 7) + (q << 4));
            off ^= (off >> 3) & 0x70;
            *(uint4*)(smem + off) = v;
        }
        // B tiles: 128 n-rows x 64 fp16, hi then lo
        for (int idx = tid; idx < 2048; idx += 256) {
            int arr = idx >> 10;
            int e = idx & 1023, row = e >> 3, q = e & 7;
            const __half* s = (arr ? Wlf : Whf) + (size_t)(n0 + row) * H1 + c * 64 + q * 8;
            uint4 v = *(const uint4*)s;
            uint32_t off = (uint32_t)((row << 7) + (q << 4));
            off ^= (off >> 3) & 0x70;
            *(uint4*)(smem + 16384 + (arr << 14) + off) = v;
        }
        __syncthreads();

#pragma unroll
        for (int ks = 0; ks < 4; ks++) {
            uint32_t ah[2][4];
#pragma unroll
            for (int mi = 0; mi < 2; mi++) {
                int rowa = warp_m * 32 + mi * 16 + (lane & 15);
                int chka = ks * 2 + (lane >> 4);
                uint32_t offa = (uint32_t)(rowa * 128 + ((chka ^ (rowa & 7)) << 4));
                LDSM_X4(ah[mi], sb + offa);
            }
#pragma unroll
            for (int nh = 0; nh < 2; nh++) {
                uint32_t bh[4][2], bl[4][2];
#pragma unroll
                for (int ni = 0; ni < 4; ni++) {
                    int rowb = warp_n * 64 + nh * 32 + ni * 8 + (lane & 7);
                    int chkb = ks * 2 + ((lane >> 3) & 1);
                    uint32_t offb = (uint32_t)(rowb * 128 + ((chkb ^ (rowb & 7)) << 4));
                    LDSM_X2(bh[ni], sb + 16384 + offb);
                    LDSM_X2(bl[ni], sb + 32768 + offb);
                }
#pragma unroll
                for (int mi = 0; mi < 2; mi++)
#pragma unroll
                    for (int ni = 0; ni < 4; ni++) {
                        float* d = acc[mi][nh * 4 + ni];
                        MMA_F16(d, ah[mi], bh[ni]);   // Xh*Wh
                        MMA_F16(d, ah[mi], bl[ni]);   // Xh*Wl
                    }
            }
        }
    }

    // Epilogue: gelu(c + b2)*W3, reduce over this CTA's 128 cols per row.
    // C frag: rows {g, g+8} (g=lane>>2), cols (lane&3)*2+{0,1}.
    const int g  = lane >> 2;
    const int cq = lane & 3;
    float rs[4] = {0.f, 0.f, 0.f, 0.f};   // rows: mi*16 + h*8 + g
#pragma unroll
    for (int mi = 0; mi < 2; mi++)
#pragma unroll
        for (int nh = 0; nh < 2; nh++)
#pragma unroll
            for (int ni = 0; ni < 4; ni++)
#pragma unroll
                for (int h = 0; h < 2; h++)
#pragma unroll
                    for (int cc = 0; cc < 2; cc++) {
                        int col = n0 + warp_n * 64 + nh * 32 + ni * 8 + cq * 2 + cc;
                        float v = gelu_exact(acc[mi][nh * 4 + ni][h * 2 + cc] + __ldg(&b2[col]))
                                  * __ldg(&W3[col]);
                        rs[mi * 2 + h] += v;
                    }
#pragma unroll
    for (int j = 0; j < 4; j++) {
        rs[j] += __shfl_xor_sync(0xffffffffu, rs[j], 1);
        rs[j] += __shfl_xor_sync(0xffffffffu, rs[j], 2);
    }
    __syncthreads();
    if (warp_n == 0 && cq == 0) {
#pragma unroll
        for (int j = 0; j < 4; j++)
            rowpart[warp_m * 32 + (j >> 1) * 16 + (j & 1) * 8 + g] = rs[j];
    }
    __syncthreads();
    if (warp_n == 1 && cq == 0) {
#pragma unroll
        for (int j = 0; j < 4; j++)
            rowpart[warp_m * 32 + (j >> 1) * 16 + (j & 1) * 8 + g] += rs[j];
    }
    __syncthreads();
    if (tid < 128)
        part[(size_t)bx * RT + r0 + tid] = rowpart[tid];
}

// out = sum of 4 col-CTA partials + b3 (deterministic fp32 combine)
__global__ void combine_k(const float* __restrict__ part, const float* __restrict__ b3,
                          float* __restrict__ out) {
    int i = blockIdx.x * 256 + threadIdx.x;
    if (i < RT)
        out[i] = part[i] + part[RT + i] + part[2 * RT + i] + part[3 * RT + i] + b3[0];
}

// ---------------------------------------------------------------------------
extern "C" void kernel_launch(void* const* d_in, const int* in_sizes, int n_in,
                              void* d_out, int out_size) {
    const float* g_q = (const float*)d_in[0];
    const float* Phi = (const float*)d_in[1];
    const float* W1  = (const float*)d_in[2];
    const float* b1  = (const float*)d_in[3];
    const float* W2  = (const float*)d_in[4];
    const float* b2  = (const float*)d_in[5];
    const float* W3  = (const float*)d_in[6];
    const float* b3  = (const float*)d_in[7];
    float* out = (float*)d_out;

    float* hz; cudaGetSymbolAddress((void**)&hz, d_hz);
    float* hp; cudaGetSymbolAddress((void**)&hp, d_hp);
    __half* Xh;  cudaGetSymbolAddress((void**)&Xh,  d_Xh);
    __half* Whf; cudaGetSymbolAddress((void**)&Whf, d_Whf);
    __half* Wlf; cudaGetSymbolAddress((void**)&Wlf, d_Wlf);
    float* part; cudaGetSymbolAddress((void**)&part, d_part);

    // First layer (small)
    gemm64<<<dim3(H1 / 64, B_ / 64), 256>>>(g_q, W1, nullptr, hz, B_, H1, DZ);
    gemm64<<<dim3(H1 / 64, M_ / 64), 256>>>(Phi, W1 + (size_t)DZ * H1, b1, hp, M_, H1, DPHI);
    // Split W2, build fp16 X
    w2_split<<<(H1 * H2 + 255) / 256, 256>>>(W2, Whf, Wlf);
    {
        size_t total4 = (size_t)RT * H1 / 4;
        build_x_h<<<(unsigned)((total4 + 255) / 256), 256>>>(Xh);
    }
    // Main HMMA GEMM (2-pass fp16) + fused gelu/W3 epilogue
    cudaFuncSetAttribute(main_mma_sync, cudaFuncAttributeMaxDynamicSharedMemorySize, MAIN_SMEM);
    main_mma_sync<<<dim3(H2 / 128, RT / 128), 256, MAIN_SMEM>>>(Xh, Whf, Wlf, b2, W3, part);
    // Combine col-CTA partials + b3
    combine_k<<<RT / 256, 256>>>(part, b3, out);
}

// round 17
// speedup vs baseline: 4.4629x; 1.3819x over previous
#include <cuda_runtime.h>
#include <cuda_fp16.h>
#include <math.h>
#include <stdint.h>

#define B_   128
#define M_   1024
#define DZ   1024
#define DPHI 512
#define H1   512
#define H2   512
#define RT   (B_*M_)          // 131072 total rows

// ---------------- scratch (__device__ globals; no allocs allowed) ----------
__device__ float d_hz[B_ * H1];                 // g_q @ W1[:DZ]
__device__ float d_hp[M_ * H1];                 // Phi @ W1[DZ:] + b1
__device__ __half d_Xh[(size_t)RT * H1];        // 134 MB : fp16(gelu(first layer))
__device__ __half d_Whf[H2 * H1];               // W2^T hi  [n][k] fp16
__device__ __half d_Wlf[H2 * H1];               // W2^T lo  [n][k] fp16
__device__ float d_part[4 * RT];                // per-col-CTA partial sums

__device__ __forceinline__ float gelu_exact(float x) {
    return 0.5f * x * (1.0f + erff(x * 0.70710678118654752f));
}
__device__ __forceinline__ uint32_t smem_u32(const void* p) {
    uint32_t a;
    asm("{ .reg .u64 t; cvta.to.shared.u64 t, %1; cvt.u32.u64 %0, t; }" : "=r"(a) : "l"(p));
    return a;
}

// Baseline (non-'a') primitives — compile for plain sm_103.
#define LDSM_X4(r, addr)                                                        \
    asm volatile("ldmatrix.sync.aligned.m8n8.x4.shared.b16 {%0,%1,%2,%3}, [%4];"\
        : "=r"((r)[0]), "=r"((r)[1]), "=r"((r)[2]), "=r"((r)[3]) : "r"(addr))
#define LDSM_X2(r, addr)                                                        \
    asm volatile("ldmatrix.sync.aligned.m8n8.x2.shared.b16 {%0,%1}, [%2];"      \
        : "=r"((r)[0]), "=r"((r)[1]) : "r"(addr))
#define MMA_F16(d, a, b)                                                        \
    asm volatile("mma.sync.aligned.m16n8k16.row.col.f32.f16.f16.f32 "           \
        "{%0,%1,%2,%3}, {%4,%5,%6,%7}, {%8,%9}, {%0,%1,%2,%3};"                 \
        : "+f"((d)[0]), "+f"((d)[1]), "+f"((d)[2]), "+f"((d)[3])                \
        : "r"((a)[0]), "r"((a)[1]), "r"((a)[2]), "r"((a)[3]),                   \
          "r"((b)[0]), "r"((b)[1]))
#define CP16(dst, src)                                                          \
    asm volatile("cp.async.cg.shared.global [%0], [%1], 16;" :: "r"(dst), "l"(src))
#define CP_COMMIT() asm volatile("cp.async.commit_group;" ::: "memory")
#define CP_WAIT(n)  asm volatile("cp.async.wait_group %0;" :: "n"(n) : "memory")

// ---------------------------------------------------------------------------
// First-layer GEMM: 64x64 tile, 256 threads, 4x4 microtile, float4 loads.
// ---------------------------------------------------------------------------
__global__ __launch_bounds__(256)
void gemm64(const float* __restrict__ A, const float* __restrict__ Bw,
            const float* __restrict__ bias, float* __restrict__ C,
            int M, int N, int K) {
    __shared__ float As[16][68];
    __shared__ float Bs[16][68];
    const int tid = threadIdx.x;
    const int tx = tid & 15;
    const int ty = tid >> 4;
    const int row0 = blockIdx.y * 64;
    const int col0 = blockIdx.x * 64;
    const int arow = tid >> 2;
    const int akq  = (tid & 3) * 4;
    const int bk   = tid >> 4;
    const int bc4  = (tid & 15) * 4;

    float acc[4][4];
#pragma unroll
    for (int i = 0; i < 4; i++)
#pragma unroll
        for (int j = 0; j < 4; j++) acc[i][j] = 0.f;

    for (int kk = 0; kk < K; kk += 16) {
        float4 av = *(const float4*)(A + (size_t)(row0 + arow) * K + kk + akq);
        float4 bv = *(const float4*)(Bw + (size_t)(kk + bk) * N + col0 + bc4);
        As[akq + 0][arow] = av.x; As[akq + 1][arow] = av.y;
        As[akq + 2][arow] = av.z; As[akq + 3][arow] = av.w;
        *(float4*)&Bs[bk][bc4] = bv;
        __syncthreads();
#pragma unroll
        for (int k = 0; k < 16; k++) {
            float4 a4 = *(const float4*)&As[k][ty * 4];
            float4 b4 = *(const float4*)&Bs[k][tx * 4];
            float a[4] = {a4.x, a4.y, a4.z, a4.w};
            float b[4] = {b4.x, b4.y, b4.z, b4.w};
#pragma unroll
            for (int i = 0; i < 4; i++)
#pragma unroll
                for (int j = 0; j < 4; j++) acc[i][j] += a[i] * b[j];
        }
        __syncthreads();
    }

    float bv[4] = {0.f, 0.f, 0.f, 0.f};
    if (bias) {
#pragma unroll
        for (int j = 0; j < 4; j++) bv[j] = bias[col0 + tx * 4 + j];
    }
#pragma unroll
    for (int i = 0; i < 4; i++) {
        float4 o;
        o.x = acc[i][0] + bv[0]; o.y = acc[i][1] + bv[1];
        o.z = acc[i][2] + bv[2]; o.w = acc[i][3] + bv[3];
        *(float4*)(C + (size_t)(row0 + ty * 4 + i) * N + col0 + tx * 4) = o;
    }
}

// ---------------------------------------------------------------------------
// X = fp16(gelu(hz[b] + hp[m])) — single array (A side needs no split).
// ---------------------------------------------------------------------------
__global__ void build_x_h(__half* __restrict__ Xh) {
    size_t i4 = (size_t)blockIdx.x * blockDim.x + threadIdx.x;
    if (i4 >= (size_t)RT * H1 / 4) return;
    int k4 = (int)(i4 & 127);
    size_t r = i4 >> 7;
    int m = (int)(r & (M_ - 1));
    int b = (int)(r >> 10);
    float4 z = ((const float4*)d_hz)[(size_t)b * 128 + k4];
    float4 p = ((const float4*)d_hp)[(size_t)m * 128 + k4];
    __half h0 = __float2half_rn(gelu_exact(z.x + p.x));
    __half h1 = __float2half_rn(gelu_exact(z.y + p.y));
    __half h2 = __float2half_rn(gelu_exact(z.z + p.z));
    __half h3 = __float2half_rn(gelu_exact(z.w + p.w));
    uint2 u;
    u.x = ((uint32_t)__half_as_ushort(h1) << 16) | __half_as_ushort(h0);
    u.y = ((uint32_t)__half_as_ushort(h3) << 16) | __half_as_ushort(h2);
    ((uint2*)Xh)[i4] = u;
}

// W2^T split into fp16 hi/lo: W = Whf + Wlf
__global__ void w2_split(const float* __restrict__ W2,
                         __half* __restrict__ Whf,
                         __half* __restrict__ Wlf) {
    int i = blockIdx.x * 256 + threadIdx.x;
    if (i >= H1 * H2) return;
    int n = i >> 9, k = i & 511;
    float w = W2[(size_t)k * H2 + n];
    __half h = __float2half_rn(w);
    __half l = __float2half_rn(w - __half2float(h));
    Whf[i] = h;
    Wlf[i] = l;
}

// ---------------------------------------------------------------------------
// Main GEMM via mma.sync fp16, cp.async DOUBLE-BUFFERED.
// CTA: 128 rows x 128 cols. 8 warps (4m x 2n), warp tile 32x64.
// K=512 in 8 chunks of 64; 2 passes (Xh*Wh + Xh*Wl).
// Stage (48KB): A@0 (16K), Bh@16K, Bl@32K. Two stages = 96KB.
// ---------------------------------------------------------------------------
#define STAGE 49152
#define MAIN_SMEM (2 * STAGE)

__global__ __launch_bounds__(256, 2)
void main_mma_sync(const __half* __restrict__ Xh,
                   const __half* __restrict__ Whf, const __half* __restrict__ Wlf,
                   const float* __restrict__ b2, const float* __restrict__ W3,
                   float* __restrict__ part) {
    extern __shared__ char smem[];
    __shared__ float rowpart[128];

    const int tid  = threadIdx.x;
    const int wid  = tid >> 5, lane = tid & 31;
    const int warp_m = wid & 3;
    const int warp_n = wid >> 2;
    const int bx = blockIdx.x;
    const int r0 = blockIdx.y << 7;
    const int n0 = bx << 7;
    const uint32_t sb = smem_u32(smem);

    // Per-thread load slots (idx = tid + 256*s)
    // A: 4 slots (1024 uint4), B: 8 slots (2048 uint4)
    uint32_t a_dst[4], b_dst[8];
    const __half* a_src_base[4];
    const __half* b_src_base[8];
#pragma unroll
    for (int s = 0; s < 4; s++) {
        int idx = tid + 256 * s;
        int row = idx >> 3, q = idx & 7;
        uint32_t off = (uint32_t)((row << 7) + (q << 4));
        off ^= (off >> 3) & 0x70;
        a_dst[s] = off;
        a_src_base[s] = d_Xh + (size_t)(r0 + row) * H1 + q * 8;
    }
#pragma unroll
    for (int s = 0; s < 8; s++) {
        int idx = tid + 256 * s;
        int arr = idx >> 10;
        int e = idx & 1023, row = e >> 3, q = e & 7;
        uint32_t off = (uint32_t)((row << 7) + (q << 4));
        off ^= (off >> 3) & 0x70;
        b_dst[s] = 16384 + ((uint32_t)arr << 14) + off;
        b_src_base[s] = (arr ? d_Wlf : d_Whf) + (size_t)(n0 + row) * H1 + q * 8;
    }

    float acc[2][8][4];
#pragma unroll
    for (int i = 0; i < 2; i++)
#pragma unroll
        for (int j = 0; j < 8; j++)
#pragma unroll
            for (int k = 0; k < 4; k++) acc[i][j][k] = 0.f;

    // Prologue: issue chunk 0 into stage 0
    {
#pragma unroll
        for (int s = 0; s < 4; s++) CP16(sb + a_dst[s], a_src_base[s]);
#pragma unroll
        for (int s = 0; s < 8; s++) CP16(sb + b_dst[s], b_src_base[s]);
        CP_COMMIT();
    }

    for (int c = 0; c < 8; c++) {
        const uint32_t cur = (uint32_t)(c & 1) * STAGE;
        if (c + 1 < 8) {
            const uint32_t nxt = (uint32_t)((c + 1) & 1) * STAGE;
            const int koff = (c + 1) * 64;
#pragma unroll
            for (int s = 0; s < 4; s++) CP16(sb + nxt + a_dst[s], a_src_base[s] + koff);
#pragma unroll
            for (int s = 0; s < 8; s++) CP16(sb + nxt + b_dst[s], b_src_base[s] + koff);
            CP_COMMIT();
            CP_WAIT(1);     // chunk c landed; chunk c+1 in flight
        } else {
            CP_WAIT(0);     // last chunk landed
        }
        __syncthreads();

#pragma unroll
        for (int ks = 0; ks < 4; ks++) {
            uint32_t ah[2][4];
#pragma unroll
            for (int mi = 0; mi < 2; mi++) {
                int rowa = warp_m * 32 + mi * 16 + (lane & 15);
                int chka = ks * 2 + (lane >> 4);
                uint32_t offa = (uint32_t)(rowa * 128 + ((chka ^ (rowa & 7)) << 4));
                LDSM_X4(ah[mi], sb + cur + offa);
            }
#pragma unroll
            for (int nh = 0; nh < 2; nh++) {
                uint32_t bh[4][2], bl[4][2];
#pragma unroll
                for (int ni = 0; ni < 4; ni++) {
                    int rowb = warp_n * 64 + nh * 32 + ni * 8 + (lane & 7);
                    int chkb = ks * 2 + ((lane >> 3) & 1);
                    uint32_t offb = (uint32_t)(rowb * 128 + ((chkb ^ (rowb & 7)) << 4));
                    LDSM_X2(bh[ni], sb + cur + 16384 + offb);
                    LDSM_X2(bl[ni], sb + cur + 32768 + offb);
                }
#pragma unroll
                for (int mi = 0; mi < 2; mi++)
#pragma unroll
                    for (int ni = 0; ni < 4; ni++) {
                        float* d = acc[mi][nh * 4 + ni];
                        MMA_F16(d, ah[mi], bh[ni]);   // Xh*Wh
                        MMA_F16(d, ah[mi], bl[ni]);   // Xh*Wl
                    }
            }
        }
        __syncthreads();   // all reads of stage `cur` done -> next issue may overwrite
    }

    // Epilogue: gelu(c + b2)*W3, reduce over this CTA's 128 cols per row.
    const int g  = lane >> 2;
    const int cq = lane & 3;
    float rs[4] = {0.f, 0.f, 0.f, 0.f};
#pragma unroll
    for (int mi = 0; mi < 2; mi++)
#pragma unroll
        for (int nh = 0; nh < 2; nh++)
#pragma unroll
            for (int ni = 0; ni < 4; ni++)
#pragma unroll
                for (int h = 0; h < 2; h++)
#pragma unroll
                    for (int cc = 0; cc < 2; cc++) {
                        int col = n0 + warp_n * 64 + nh * 32 + ni * 8 + cq * 2 + cc;
                        float v = gelu_exact(acc[mi][nh * 4 + ni][h * 2 + cc] + __ldg(&b2[col]))
                                  * __ldg(&W3[col]);
                        rs[mi * 2 + h] += v;
                    }
#pragma unroll
    for (int j = 0; j < 4; j++) {
        rs[j] += __shfl_xor_sync(0xffffffffu, rs[j], 1);
        rs[j] += __shfl_xor_sync(0xffffffffu, rs[j], 2);
    }
    __syncthreads();
    if (warp_n == 0 && cq == 0) {
#pragma unroll
        for (int j = 0; j < 4; j++)
            rowpart[warp_m * 32 + (j >> 1) * 16 + (j & 1) * 8 + g] = rs[j];
    }
    __syncthreads();
    if (warp_n == 1 && cq == 0) {
#pragma unroll
        for (int j = 0; j < 4; j++)
            rowpart[warp_m * 32 + (j >> 1) * 16 + (j & 1) * 8 + g] += rs[j];
    }
    __syncthreads();
    if (tid < 128)
        part[(size_t)bx * RT + r0 + tid] = rowpart[tid];
}

// out = sum of 4 col-CTA partials + b3 (deterministic fp32 combine)
__global__ void combine_k(const float* __restrict__ part, const float* __restrict__ b3,
                          float* __restrict__ out) {
    int i = blockIdx.x * 256 + threadIdx.x;
    if (i < RT)
        out[i] = part[i] + part[RT + i] + part[2 * RT + i] + part[3 * RT + i] + b3[0];
}

// ---------------------------------------------------------------------------
extern "C" void kernel_launch(void* const* d_in, const int* in_sizes, int n_in,
                              void* d_out, int out_size) {
    const float* g_q = (const float*)d_in[0];
    const float* Phi = (const float*)d_in[1];
    const float* W1  = (const float*)d_in[2];
    const float* b1  = (const float*)d_in[3];
    const float* W2  = (const float*)d_in[4];
    const float* b2  = (const float*)d_in[5];
    const float* W3  = (const float*)d_in[6];
    const float* b3  = (const float*)d_in[7];
    float* out = (float*)d_out;

    float* hz; cudaGetSymbolAddress((void**)&hz, d_hz);
    float* hp; cudaGetSymbolAddress((void**)&hp, d_hp);
    __half* Xh;  cudaGetSymbolAddress((void**)&Xh,  d_Xh);
    __half* Whf; cudaGetSymbolAddress((void**)&Whf, d_Whf);
    __half* Wlf; cudaGetSymbolAddress((void**)&Wlf, d_Wlf);
    float* part; cudaGetSymbolAddress((void**)&part, d_part);

    // First layer (small)
    gemm64<<<dim3(H1 / 64, B_ / 64), 256>>>(g_q, W1, nullptr, hz, B_, H1, DZ);
    gemm64<<<dim3(H1 / 64, M_ / 64), 256>>>(Phi, W1 + (size_t)DZ * H1, b1, hp, M_, H1, DPHI);
    // Split W2, build fp16 X
    w2_split<<<(H1 * H2 + 255) / 256, 256>>>(W2, Whf, Wlf);
    {
        size_t total4 = (size_t)RT * H1 / 4;
        build_x_h<<<(unsigned)((total4 + 255) / 256), 256>>>(Xh);
    }
    // Main HMMA GEMM (2-pass fp16, cp.async double-buffered) + fused epilogue
    cudaFuncSetAttribute(main_mma_sync, cudaFuncAttributeMaxDynamicSharedMemorySize, MAIN_SMEM);
    main_mma_sync<<<dim3(H2 / 128, RT / 128), 256, MAIN_SMEM>>>(Xh, Whf, Wlf, b2, W3, part);
    // Combine col-CTA partials + b3
    combine_k<<<RT / 256, 256>>>(part, b3, out);
}